// round 3
// baseline (speedup 1.0000x reference)
#include <cuda_runtime.h>

#define BB    64
#define SS    1024
#define HH    1000
#define SPLIT 8
#define CHUNK (SS / SPLIT)   /* 128 rows per CTA */
#define TILE  8              /* rows per smem tile (36KB smem -> 4 CTAs/SM, 1 wave) */
#define NT    256
#define H4    250            /* float4 per row */

#define NGS   16             /* g-splits for v kernel */
#define GPS   63             /* g per split (16*63 >= 1000) */

// Scratch (static device arrays: allocation-free per harness rules)
__device__ float g_vp[NGS * BB * HH];        // 4 MB   v partials
__device__ float g_v[BB * HH];               // 256 KB v = h_tgt @ W
__device__ float g_part[SPLIT * BB * HH];    // 2 MB   unnormalized acc per split
__device__ float g_ml[SPLIT * BB * 2];       // (m, l) per split

// ---------------------------------------------------------------------------
// Kernel 1: v partials.  grid (16 h-chunks, 16 g-splits), 256 threads.
// Each block: 64 h-cols x all 64 b x 63 g. Register blocking 4b x 4h(float4).
// W is read exactly once from DRAM across the whole grid.
// ---------------------------------------------------------------------------
__global__ __launch_bounds__(256) void v_partial_kernel(
    const float* __restrict__ h_tgt, const float* __restrict__ Wm)
{
    __shared__ float stg[64 * GPS];   // h_tgt tile [b][gi]
    const int hb = blockIdx.x;        // 0..15
    const int gs = blockIdx.y;        // 0..15
    const int h0 = hb * 64;
    const int g0 = gs * GPS;
    const int gcnt = min(GPS, HH - g0);
    const int t = threadIdx.x;

    for (int idx = t; idx < 64 * GPS; idx += 256) {
        int b  = idx / GPS;
        int gi = idx - b * GPS;
        int g  = g0 + gi;
        stg[idx] = (g < HH) ? h_tgt[b * HH + g] : 0.f;
    }
    __syncthreads();

    const int hq = t & 15;            // h quad within chunk
    const int bg = t >> 4;            // 16 groups of 4 batches
    const int h  = h0 + hq * 4;
    const bool hok = (h + 3) < HH;

    if (hok) {
        float4 acc[4];
        #pragma unroll
        for (int i = 0; i < 4; i++) acc[i] = make_float4(0.f, 0.f, 0.f, 0.f);

        for (int gi = 0; gi < gcnt; gi++) {
            float4 w4 = __ldg((const float4*)(Wm + (size_t)(g0 + gi) * HH + h));
            #pragma unroll
            for (int bb = 0; bb < 4; bb++) {
                float tb = stg[(bg * 4 + bb) * GPS + gi];   // 2-addr broadcast
                acc[bb].x += tb * w4.x;
                acc[bb].y += tb * w4.y;
                acc[bb].z += tb * w4.z;
                acc[bb].w += tb * w4.w;
            }
        }
        #pragma unroll
        for (int bb = 0; bb < 4; bb++) {
            int b = bg * 4 + bb;
            *((float4*)(g_vp + (size_t)gs * (BB * HH) + b * HH + h)) = acc[bb];
        }
    }
}

// ---------------------------------------------------------------------------
// Kernel 2: reduce v partials. 250 blocks x 256 = 64000 threads.
// ---------------------------------------------------------------------------
__global__ __launch_bounds__(256) void v_reduce_kernel()
{
    int i = blockIdx.x * 256 + threadIdx.x;   // exactly BB*HH
    float s = 0.f;
    #pragma unroll
    for (int gs = 0; gs < NGS; gs++) s += g_vp[gs * (BB * HH) + i];
    g_v[i] = s;
}

// ---------------------------------------------------------------------------
// Kernel 3: single-pass online-softmax attention over a CHUNK of S.
// grid (SPLIT, B) = 512 CTAs, 256 thr, ~36 KB smem -> 4 CTAs/SM, ONE wave.
// h_src read ONCE from DRAM. Cross-CTA phase interleave hides load latency.
// ---------------------------------------------------------------------------
__global__ __launch_bounds__(256, 4) void attn_main_kernel(const float* __restrict__ h_src)
{
    extern __shared__ float sm[];
    float* sv    = sm;                 // [1000] v for this batch
    float* stile = sm + 1000;          // [TILE * 1000] current tile
    float* ss    = sm + 1000 + TILE * HH;  // [TILE] scores

    const int sp = blockIdx.x, b = blockIdx.y;
    const int t = threadIdx.x, lane = t & 31, warp = t >> 5;
    const float* src = h_src + ((size_t)b * SS + (size_t)sp * CHUNK) * HH;

    for (int i = t; i < HH; i += NT) sv[i] = g_v[b * HH + i];

    const float4* sv4 = (const float4*)sv;

    float m = -1e30f, l = 0.f;
    float4 acc = make_float4(0.f, 0.f, 0.f, 0.f);

    for (int ti = 0; ti < CHUNK / TILE; ++ti) {
        __syncthreads();   // previous tile fully consumed (also covers sv init)
        // Load TILE contiguous rows = 2000 float4 (coalesced)
        const float4* gs4 = (const float4*)(src + (size_t)ti * TILE * HH);
        float4* st4 = (float4*)stile;
        #pragma unroll 4
        for (int i = t; i < TILE * H4; i += NT) st4[i] = gs4[i];
        __syncthreads();

        // Scores: one row per warp, float4 LDS for both tile row and v
        {
            const int r = warp;        // TILE == warps == 8
            const float4* row4 = (const float4*)(stile + r * HH);
            float s = 0.f;
            #pragma unroll
            for (int j = 0; j < 7; j++) {
                float4 a = row4[lane + 32 * j];
                float4 v = sv4[lane + 32 * j];
                s += a.x * v.x + a.y * v.y + a.z * v.z + a.w * v.w;
            }
            if (lane < 26) {           // 250 = 7*32 + 26
                float4 a = row4[224 + lane];
                float4 v = sv4[224 + lane];
                s += a.x * v.x + a.y * v.y + a.z * v.z + a.w * v.w;
            }
            #pragma unroll
            for (int o = 16; o; o >>= 1) s += __shfl_xor_sync(0xffffffffu, s, o);
            if (lane == 0) ss[r] = s;
        }
        __syncthreads();

        // Online softmax update (computed redundantly & identically per thread)
        float tm = ss[0];
        #pragma unroll
        for (int i = 1; i < TILE; i++) tm = fmaxf(tm, ss[i]);
        float nm   = fmaxf(m, tm);
        float corr = __expf(m - nm);
        float p[TILE];
        float tls = 0.f;
        #pragma unroll
        for (int i = 0; i < TILE; i++) { p[i] = __expf(ss[i] - nm); tls += p[i]; }
        m = nm;
        l = l * corr + tls;
        acc.x *= corr; acc.y *= corr; acc.z *= corr; acc.w *= corr;

        // Accumulate weighted rows: thread t owns h in [4t, 4t+4)
        if (t < H4) {
            const float4* tp = (const float4*)stile;
            #pragma unroll
            for (int i = 0; i < TILE; i++) {
                float4 x = tp[i * H4 + t];
                acc.x += p[i] * x.x;
                acc.y += p[i] * x.y;
                acc.z += p[i] * x.z;
                acc.w += p[i] * x.w;
            }
        }
    }

    if (t < H4)
        *((float4*)(g_part + (size_t)(sp * BB + b) * HH) + t) = acc;
    if (t == 0) {
        g_ml[(sp * BB + b) * 2]     = m;
        g_ml[(sp * BB + b) * 2 + 1] = l;
    }
}

// ---------------------------------------------------------------------------
// Kernel 4: combine SPLIT partials per batch (log-sum-exp merge) -> output.
// ---------------------------------------------------------------------------
__global__ __launch_bounds__(256) void combine_kernel(float* __restrict__ out)
{
    const int b = blockIdx.x, t = threadIdx.x;
    __shared__ float shm[SPLIT], shl[SPLIT];
    if (t < SPLIT) {
        shm[t] = g_ml[(t * BB + b) * 2];
        shl[t] = g_ml[(t * BB + b) * 2 + 1];
    }
    __syncthreads();

    float M = shm[0];
    #pragma unroll
    for (int i = 1; i < SPLIT; i++) M = fmaxf(M, shm[i]);
    float w[SPLIT];
    float L = 0.f;
    #pragma unroll
    for (int i = 0; i < SPLIT; i++) { w[i] = __expf(shm[i] - M); L += shl[i] * w[i]; }
    const float inv = 1.f / L;

    if (t < H4) {
        float4 o = make_float4(0.f, 0.f, 0.f, 0.f);
        #pragma unroll
        for (int i = 0; i < SPLIT; i++) {
            float4 x = *((const float4*)(g_part + (size_t)(i * BB + b) * HH) + t);
            o.x += w[i] * x.x;
            o.y += w[i] * x.y;
            o.z += w[i] * x.z;
            o.w += w[i] * x.w;
        }
        o.x *= inv; o.y *= inv; o.z *= inv; o.w *= inv;
        *((float4*)(out + (size_t)b * HH) + t) = o;
    }
}

// ---------------------------------------------------------------------------
extern "C" void kernel_launch(void* const* d_in, const int* in_sizes, int n_in,
                              void* d_out, int out_size)
{
    const float* h_tgt = (const float*)d_in[0];   // [64, 1, 1000]
    const float* h_src = (const float*)d_in[1];   // [64, 1024, 1000]
    const float* Wm    = (const float*)d_in[2];   // [1000, 1000]
    // d_in[3] = bias: provably cancels under softmax shift-invariance; unused.
    float* out = (float*)d_out;                   // [64, 1, 1000]

    const int smem_main = (1000 + TILE * HH + TILE) * 4 + 64;   // ~36 KB
    cudaFuncSetAttribute(attn_main_kernel,
                         cudaFuncAttributeMaxDynamicSharedMemorySize, smem_main);

    v_partial_kernel<<<dim3(16, NGS), 256>>>(h_tgt, Wm);
    v_reduce_kernel<<<(BB * HH) / 256, 256>>>();
    attn_main_kernel<<<dim3(SPLIT, BB), 256, smem_main>>>(h_src);
    combine_kernel<<<BB, 256>>>(out);
}

// round 5
// speedup vs baseline: 1.0874x; 1.0874x over previous
#include <cuda_runtime.h>
#include <cstdint>

#define BB    64
#define SS    1024
#define HH    1000
#define SPLIT 8
#define CHUNK (SS / SPLIT)   /* 128 rows per CTA */
#define TILE  8              /* rows per buffer */
#define NTILES (CHUNK / TILE)
#define NT    256
#define H4    250            /* float4 per row */
#define TILE4 (TILE * H4)    /* 2000 float4 per tile */

#define NGS   16
#define GPS   63

// Scratch (static device arrays: allocation-free per harness rules)
__device__ float g_vp[NGS * BB * HH];        // 4 MB   v partials
__device__ float g_v[BB * HH];               // 256 KB v = h_tgt @ W
__device__ float g_part[SPLIT * BB * HH];    // 2 MB   unnormalized acc per split
__device__ float g_ml[SPLIT * BB * 2];       // (m, l) per split

__device__ __forceinline__ void cp_async16(void* smem_dst, const void* gmem_src) {
    uint32_t s = (uint32_t)__cvta_generic_to_shared(smem_dst);
    asm volatile("cp.async.cg.shared.global [%0], [%1], 16;\n" :: "r"(s), "l"(gmem_src));
}
#define CP_COMMIT()  asm volatile("cp.async.commit_group;\n" ::: "memory")
#define CP_WAIT(n)   asm volatile("cp.async.wait_group %0;\n" :: "n"(n) : "memory")

// ---------------------------------------------------------------------------
// Kernel 1: v partials.  grid (16 h-chunks, 16 g-splits), 256 threads.
// ---------------------------------------------------------------------------
__global__ __launch_bounds__(256) void v_partial_kernel(
    const float* __restrict__ h_tgt, const float* __restrict__ Wm)
{
    __shared__ float stg[64 * GPS];
    const int hb = blockIdx.x, gs = blockIdx.y;
    const int h0 = hb * 64, g0 = gs * GPS;
    const int gcnt = min(GPS, HH - g0);
    const int t = threadIdx.x;

    for (int idx = t; idx < 64 * GPS; idx += 256) {
        int b  = idx / GPS;
        int gi = idx - b * GPS;
        int g  = g0 + gi;
        stg[idx] = (g < HH) ? h_tgt[b * HH + g] : 0.f;
    }
    __syncthreads();

    const int hq = t & 15, bg = t >> 4;
    const int h  = h0 + hq * 4;
    if ((h + 3) < HH) {
        float4 acc[4];
        #pragma unroll
        for (int i = 0; i < 4; i++) acc[i] = make_float4(0.f, 0.f, 0.f, 0.f);

        for (int gi = 0; gi < gcnt; gi++) {
            float4 w4 = __ldg((const float4*)(Wm + (size_t)(g0 + gi) * HH + h));
            #pragma unroll
            for (int bb = 0; bb < 4; bb++) {
                float tb = stg[(bg * 4 + bb) * GPS + gi];
                acc[bb].x += tb * w4.x;
                acc[bb].y += tb * w4.y;
                acc[bb].z += tb * w4.z;
                acc[bb].w += tb * w4.w;
            }
        }
        #pragma unroll
        for (int bb = 0; bb < 4; bb++) {
            int b = bg * 4 + bb;
            *((float4*)(g_vp + (size_t)gs * (BB * HH) + b * HH + h)) = acc[bb];
        }
    }
}

// ---------------------------------------------------------------------------
// Kernel 2: reduce v partials.
// ---------------------------------------------------------------------------
__global__ __launch_bounds__(256) void v_reduce_kernel()
{
    int i = blockIdx.x * 256 + threadIdx.x;
    float s = 0.f;
    #pragma unroll
    for (int gs = 0; gs < NGS; gs++) s += g_vp[gs * (BB * HH) + i];
    g_v[i] = s;
}

// ---------------------------------------------------------------------------
// Kernel 3: single-pass online-softmax attention, cp.async double-buffered.
// grid (SPLIT, BB) = 512 CTAs, 256 thr, ~68 KB smem (3 CTAs/SM).
// While tile i is scored/accumulated, tile i+1 streams in via LDGSTS:
// global loads are ALWAYS in flight -> DRAM stays saturated.
// ---------------------------------------------------------------------------
__global__ __launch_bounds__(256) void attn_main_kernel(const float* __restrict__ h_src)
{
    extern __shared__ float sm[];
    float* sv = sm;                         // [1000]
    float* ss = sm + 1000 + 2 * (TILE * HH);// [8] scores
    float4* bufA = (float4*)(sm + 1000);             // tile buffer 0
    float4* bufB = (float4*)(sm + 1000 + TILE * HH); // tile buffer 1

    const int sp = blockIdx.x, b = blockIdx.y;
    const int t = threadIdx.x, lane = t & 31, warp = t >> 5;
    const float4* src4 = (const float4*)(h_src + ((size_t)b * SS + (size_t)sp * CHUNK) * HH);

    // Prefetch tile 0 into bufA
    for (int i = t; i < TILE4; i += NT) cp_async16(bufA + i, src4 + i);
    CP_COMMIT();

    // Stage v while tile 0 is in flight
    for (int i = t; i < HH; i += NT) sv[i] = g_v[b * HH + i];
    __syncthreads();

    // v in registers (lane-strided): halves score-phase smem traffic
    const float4* sv4 = (const float4*)sv;
    float4 vk[8];
    #pragma unroll
    for (int j = 0; j < 7; j++) vk[j] = sv4[lane + 32 * j];
    vk[7] = (lane < 26) ? sv4[224 + lane] : make_float4(0.f, 0.f, 0.f, 0.f);

    float m = -1e30f, l = 0.f;
    float4 acc = make_float4(0.f, 0.f, 0.f, 0.f);
    float4* cur = bufA;
    float4* nxt = bufB;

    #pragma unroll 1
    for (int ti = 0; ti < NTILES; ++ti) {
        // Issue next tile, then wait for current (leave newest group in flight)
        if (ti + 1 < NTILES) {
            const float4* g = src4 + (size_t)(ti + 1) * TILE4;
            for (int i = t; i < TILE4; i += NT) cp_async16(nxt + i, g + i);
            CP_COMMIT();
            CP_WAIT(1);
        } else {
            CP_WAIT(0);
        }
        __syncthreads();   // current tile visible to all threads

        // Score: warp w owns row w (8 warps == TILE rows)
        {
            const float4* row4 = cur + warp * H4;
            float s = 0.f;
            #pragma unroll
            for (int j = 0; j < 7; j++) {
                float4 a = row4[lane + 32 * j];
                s += a.x * vk[j].x + a.y * vk[j].y + a.z * vk[j].z + a.w * vk[j].w;
            }
            if (lane < 26) {
                float4 a = row4[224 + lane];
                s += a.x * vk[7].x + a.y * vk[7].y + a.z * vk[7].z + a.w * vk[7].w;
            }
            #pragma unroll
            for (int o = 16; o; o >>= 1) s += __shfl_xor_sync(0xffffffffu, s, o);
            if (lane == 0) ss[warp] = s;
        }
        __syncthreads();

        // Online softmax update (redundant & identical per thread)
        float tm = ss[0];
        #pragma unroll
        for (int i = 1; i < TILE; i++) tm = fmaxf(tm, ss[i]);
        float nm   = fmaxf(m, tm);
        float corr = __expf(m - nm);
        float p[TILE];
        float tls = 0.f;
        #pragma unroll
        for (int i = 0; i < TILE; i++) { p[i] = __expf(ss[i] - nm); tls += p[i]; }
        m = nm;
        l = l * corr + tls;
        acc.x *= corr; acc.y *= corr; acc.z *= corr; acc.w *= corr;

        // Accumulate: thread t owns h4 slot t
        if (t < H4) {
            #pragma unroll
            for (int i = 0; i < TILE; i++) {
                float4 x = cur[i * H4 + t];
                acc.x += p[i] * x.x;
                acc.y += p[i] * x.y;
                acc.z += p[i] * x.z;
                acc.w += p[i] * x.w;
            }
        }
        __syncthreads();   // cur fully consumed before next iter overwrites it

        float4* tmp = cur; cur = nxt; nxt = tmp;
    }

    if (t < H4)
        *((float4*)(g_part + (size_t)(sp * BB + b) * HH) + t) = acc;
    if (t == 0) {
        g_ml[(sp * BB + b) * 2]     = m;
        g_ml[(sp * BB + b) * 2 + 1] = l;
    }
}

// ---------------------------------------------------------------------------
// Kernel 4: combine SPLIT partials (log-sum-exp merge) -> output.
// grid (BB, 5) x 64 threads: 320 blocks to beat latency-boundedness.
// ---------------------------------------------------------------------------
__global__ __launch_bounds__(64) void combine_kernel(float* __restrict__ out)
{
    const int b = blockIdx.x;
    const int h4 = blockIdx.y * 50 + threadIdx.x;   // 5 * 50 = 250 slots
    if (threadIdx.x >= 50) return;

    float mv[SPLIT], lv[SPLIT];
    #pragma unroll
    for (int i = 0; i < SPLIT; i++) {
        mv[i] = g_ml[(i * BB + b) * 2];
        lv[i] = g_ml[(i * BB + b) * 2 + 1];
    }
    float M = mv[0];
    #pragma unroll
    for (int i = 1; i < SPLIT; i++) M = fmaxf(M, mv[i]);
    float w[SPLIT];
    float L = 0.f;
    #pragma unroll
    for (int i = 0; i < SPLIT; i++) { w[i] = __expf(mv[i] - M); L += lv[i] * w[i]; }
    const float inv = 1.f / L;

    float4 o = make_float4(0.f, 0.f, 0.f, 0.f);
    #pragma unroll
    for (int i = 0; i < SPLIT; i++) {
        float4 x = *((const float4*)(g_part + (size_t)(i * BB + b) * HH) + h4);
        o.x += w[i] * x.x;
        o.y += w[i] * x.y;
        o.z += w[i] * x.z;
        o.w += w[i] * x.w;
    }
    o.x *= inv; o.y *= inv; o.z *= inv; o.w *= inv;
    *((float4*)(out + (size_t)b * HH) + h4) = o;
}

// ---------------------------------------------------------------------------
extern "C" void kernel_launch(void* const* d_in, const int* in_sizes, int n_in,
                              void* d_out, int out_size)
{
    const float* h_tgt = (const float*)d_in[0];   // [64, 1, 1000]
    const float* h_src = (const float*)d_in[1];   // [64, 1024, 1000]
    const float* Wm    = (const float*)d_in[2];   // [1000, 1000]
    // d_in[3] = bias: cancels under softmax shift-invariance; unused.
    float* out = (float*)d_out;                   // [64, 1, 1000]

    const int smem_main = (1000 + 2 * TILE * HH + TILE) * 4 + 64;   // ~68 KB
    cudaFuncSetAttribute(attn_main_kernel,
                         cudaFuncAttributeMaxDynamicSharedMemorySize, smem_main);

    v_partial_kernel<<<dim3(16, NGS), 256>>>(h_tgt, Wm);
    v_reduce_kernel<<<(BB * HH) / 256, 256>>>();
    attn_main_kernel<<<dim3(SPLIT, BB), 256, smem_main>>>(h_src);
    combine_kernel<<<dim3(BB, 5), 64>>>(out);
}